// round 2
// baseline (speedup 1.0000x reference)
#include <cuda_runtime.h>
#include <math.h>

// Problem constants
#define M_TOK 16384   // B*T = 8*2048
#define V_DIM 4096
#define C_DIM 128
#define K_NB2 128     // 2*NB
#define N_OPS 8

// Scratch (no allocation allowed -> device globals)
__device__ float g_rw[V_DIM * C_DIM];     // read_w (after col-softmax)
__device__ float g_ww[V_DIM * C_DIM];     // write_w
__device__ float g_vals[M_TOK * C_DIM];   // values = x @ read_w
__device__ float g_mix[M_TOK * C_DIM];    // op-bank output

// ---------------------------------------------------------------------------
// Generic tiled SGEMM. BT=false: C = A(MxK) @ B(KxN).  BT=true: C = A @ B^T,
// with B stored (N x K) row-major. alpha_ptr==nullptr -> alpha=1.
// ---------------------------------------------------------------------------
template <int BM, int BN, int BK, int TM, int TN, bool BT>
__global__ __launch_bounds__(256) void sgemm(
    const float* __restrict__ A, const float* __restrict__ B,
    float* __restrict__ Cm, int M, int N, int K,
    const float* __restrict__ alpha_ptr)
{
    __shared__ float As[BK][BM];
    __shared__ float Bs[BK][BN];

    constexpr int THREADS = (BM / TM) * (BN / TN);
    const int tid = threadIdx.x;
    const int tcn = BN / TN;
    const int tc = tid % tcn;
    const int tr = tid / tcn;
    const int m0 = blockIdx.y * BM;
    const int n0 = blockIdx.x * BN;

    float acc[TM][TN];
#pragma unroll
    for (int i = 0; i < TM; i++)
#pragma unroll
        for (int j = 0; j < TN; j++) acc[i][j] = 0.0f;

    for (int k0 = 0; k0 < K; k0 += BK) {
        // Load A tile (BM x BK), store transposed As[k][m]
        constexpr int AV = BM * BK / 4 / THREADS;
#pragma unroll
        for (int i = 0; i < AV; i++) {
            int idx = tid + i * THREADS;
            int row = idx / (BK / 4);
            int c4  = idx % (BK / 4);
            const float4 v = *(const float4*)&A[(size_t)(m0 + row) * K + k0 + c4 * 4];
            As[c4 * 4 + 0][row] = v.x;
            As[c4 * 4 + 1][row] = v.y;
            As[c4 * 4 + 2][row] = v.z;
            As[c4 * 4 + 3][row] = v.w;
        }
        if (BT) {
            // B is (N x K): load BN rows x BK cols, store transposed Bs[k][n]
            constexpr int BV = BN * BK / 4 / THREADS;
#pragma unroll
            for (int i = 0; i < BV; i++) {
                int idx = tid + i * THREADS;
                int row = idx / (BK / 4);
                int c4  = idx % (BK / 4);
                const float4 v = *(const float4*)&B[(size_t)(n0 + row) * K + k0 + c4 * 4];
                Bs[c4 * 4 + 0][row] = v.x;
                Bs[c4 * 4 + 1][row] = v.y;
                Bs[c4 * 4 + 2][row] = v.z;
                Bs[c4 * 4 + 3][row] = v.w;
            }
        } else {
            // B is (K x N): direct coalesced copy Bs[k][n]
            constexpr int BV = BK * BN / 4 / THREADS;
#pragma unroll
            for (int i = 0; i < BV; i++) {
                int idx = tid + i * THREADS;
                int row = idx / (BN / 4);
                int c4  = idx % (BN / 4);
                *(float4*)&Bs[row][c4 * 4] =
                    *(const float4*)&B[(size_t)(k0 + row) * N + n0 + c4 * 4];
            }
        }
        __syncthreads();

#pragma unroll
        for (int k = 0; k < BK; k++) {
            float ra[TM], rb[TN];
#pragma unroll
            for (int i = 0; i < TM; i++) ra[i] = As[k][tr * TM + i];
#pragma unroll
            for (int j = 0; j < TN; j++) rb[j] = Bs[k][tc * TN + j];
#pragma unroll
            for (int i = 0; i < TM; i++)
#pragma unroll
                for (int j = 0; j < TN; j++) acc[i][j] += ra[i] * rb[j];
        }
        __syncthreads();
    }

    const float alpha = alpha_ptr ? __ldg(alpha_ptr) : 1.0f;
#pragma unroll
    for (int i = 0; i < TM; i++) {
        const size_t base = (size_t)(m0 + tr * TM + i) * N + n0 + tc * TN;
#pragma unroll
        for (int j = 0; j < TN; j++) Cm[base + j] = acc[i][j] * alpha;
    }
}

// ---------------------------------------------------------------------------
// In-place softmax over rows (axis 0) of S (V_DIM x C_DIM), one block/column.
// ---------------------------------------------------------------------------
__global__ __launch_bounds__(256) void col_softmax(float* __restrict__ S)
{
    __shared__ float col[V_DIM];
    __shared__ float red[256];
    const int c = blockIdx.x;
    const int tid = threadIdx.x;

    float m = -1e30f;
    for (int v = tid; v < V_DIM; v += 256) {
        float x = S[(size_t)v * C_DIM + c];
        col[v] = x;
        m = fmaxf(m, x);
    }
    red[tid] = m;
    __syncthreads();
    for (int s = 128; s > 0; s >>= 1) {
        if (tid < s) red[tid] = fmaxf(red[tid], red[tid + s]);
        __syncthreads();
    }
    m = red[0];
    __syncthreads();

    float sum = 0.0f;
    for (int v = tid; v < V_DIM; v += 256) {
        float e = expf(col[v] - m);
        col[v] = e;
        sum += e;
    }
    red[tid] = sum;
    __syncthreads();
    for (int s = 128; s > 0; s >>= 1) {
        if (tid < s) red[tid] += red[tid + s];
        __syncthreads();
    }
    const float inv = 1.0f / red[0];
    for (int v = tid; v < V_DIM; v += 256)
        S[(size_t)v * C_DIM + c] = col[v] * inv;
}

// ---------------------------------------------------------------------------
// Fused op-bank: mixed = sum_i softmax(logits)[i] * f_i(values @ W_i + b_i)
// Block: 64 rows x 128 cols, 256 threads, thread tile 4x8.
// ---------------------------------------------------------------------------
__global__ __launch_bounds__(256) void opbank(
    const float* __restrict__ vals, const float* __restrict__ logits,
    const float* __restrict__ W, const float* __restrict__ bias,
    float* __restrict__ outv)
{
    __shared__ float vT[C_DIM][64];   // values tile, k-major
    __shared__ float Ws[16][C_DIM];   // 16-row K slab of W_i

    const int tid = threadIdx.x;
    const int tc = tid % 16;          // 16 col-groups of 8
    const int tr = tid / 16;          // 16 row-groups of 4
    const int m0 = blockIdx.x * 64;

    // Load 64x128 values tile, transposed
#pragma unroll
    for (int i = 0; i < 8; i++) {
        int idx = tid + i * 256;      // float4 index in 64x32
        int row = idx / 32;
        int c4  = idx % 32;
        const float4 v = *(const float4*)&vals[(size_t)(m0 + row) * C_DIM + c4 * 4];
        vT[c4 * 4 + 0][row] = v.x;
        vT[c4 * 4 + 1][row] = v.y;
        vT[c4 * 4 + 2][row] = v.z;
        vT[c4 * 4 + 3][row] = v.w;
    }

    // Softmax of op logits (tiny, per-thread)
    float wl[N_OPS];
    float mx = -1e30f;
#pragma unroll
    for (int i = 0; i < N_OPS; i++) { wl[i] = __ldg(&logits[i]); mx = fmaxf(mx, wl[i]); }
    float ws = 0.0f;
#pragma unroll
    for (int i = 0; i < N_OPS; i++) { wl[i] = expf(wl[i] - mx); ws += wl[i]; }
    const float wsi = 1.0f / ws;
#pragma unroll
    for (int i = 0; i < N_OPS; i++) wl[i] *= wsi;

    float res[4][8];
#pragma unroll
    for (int i = 0; i < 4; i++)
#pragma unroll
        for (int j = 0; j < 8; j++) res[i][j] = 0.0f;

    __syncthreads();

    for (int op = 0; op < N_OPS; op++) {
        const float* Wop = W + (size_t)op * C_DIM * C_DIM;
        float h[4][8];
#pragma unroll
        for (int i = 0; i < 4; i++)
#pragma unroll
            for (int j = 0; j < 8; j++) h[i][j] = 0.0f;

        for (int kt = 0; kt < 8; kt++) {
            __syncthreads();
#pragma unroll
            for (int i = 0; i < 2; i++) {
                int idx = tid + i * 256;  // float4 index in 16x32
                int row = idx / 32;
                int c4  = idx % 32;
                *(float4*)&Ws[row][c4 * 4] =
                    *(const float4*)&Wop[(size_t)(kt * 16 + row) * C_DIM + c4 * 4];
            }
            __syncthreads();
#pragma unroll
            for (int k = 0; k < 16; k++) {
                float ra[4], rb[8];
#pragma unroll
                for (int i = 0; i < 4; i++) ra[i] = vT[kt * 16 + k][tr * 4 + i];
#pragma unroll
                for (int j = 0; j < 8; j++) rb[j] = Ws[k][tc * 8 + j];
#pragma unroll
                for (int i = 0; i < 4; i++)
#pragma unroll
                    for (int j = 0; j < 8; j++) h[i][j] += ra[i] * rb[j];
            }
        }

        const float wo = wl[op];
#pragma unroll
        for (int j = 0; j < 8; j++) {
            const float b = __ldg(&bias[op * C_DIM + tc * 8 + j]);
#pragma unroll
            for (int i = 0; i < 4; i++) {
                float v = h[i][j] + b;
                float f;
                switch (op) {
                    case 0: f = v; break;
                    case 1: f = fmaxf(v, 0.0f); break;
                    case 2: f = 0.5f * v * (1.0f + erff(v * 0.70710678118654752f)); break;
                    case 3: f = v * v; break;
                    case 4: f = -v; break;
                    case 5: f = fabsf(v); break;
                    case 6: f = tanhf(v); break;
                    default: f = 1.0f / (1.0f + expf(-v)); break;
                }
                res[i][j] += wo * f;
            }
        }
    }

#pragma unroll
    for (int i = 0; i < 4; i++) {
        const size_t base = (size_t)(m0 + tr * 4 + i) * C_DIM + tc * 8;
#pragma unroll
        for (int j = 0; j < 8; j++) outv[base + j] = res[i][j];
    }
}

// ---------------------------------------------------------------------------
extern "C" void kernel_launch(void* const* d_in, const int* in_sizes, int n_in,
                              void* d_out, int out_size)
{
    const float* x      = (const float*)d_in[0];   // (16384, 4096)
    const float* basis  = (const float*)d_in[1];   // (4096, 128)
    const float* rcoef  = (const float*)d_in[2];   // (128, 128)
    const float* wcoef  = (const float*)d_in[3];   // (128, 128)
    const float* logits = (const float*)d_in[4];   // (8,)
    const float* opW    = (const float*)d_in[5];   // (8, 128, 128)
    const float* opB    = (const float*)d_in[6];   // (8, 128)
    const float* oscale = (const float*)d_in[7];   // scalar
    float* out = (float*)d_out;                    // (16384, 4096)

    float *p_rw, *p_ww, *p_vals, *p_mix;
    cudaGetSymbolAddress((void**)&p_rw,   g_rw);
    cudaGetSymbolAddress((void**)&p_ww,   g_ww);
    cudaGetSymbolAddress((void**)&p_vals, g_vals);
    cudaGetSymbolAddress((void**)&p_mix,  g_mix);

    // 1) addressing scores: S = basis @ coeffs^T  (V x C)
    {
        dim3 grid(C_DIM / 128, V_DIM / 128);
        sgemm<128, 128, 16, 8, 8, true><<<grid, 256>>>(
            basis, rcoef, p_rw, V_DIM, C_DIM, K_NB2, nullptr);
        sgemm<128, 128, 16, 8, 8, true><<<grid, 256>>>(
            basis, wcoef, p_ww, V_DIM, C_DIM, K_NB2, nullptr);
    }

    // 2) read_w = softmax over V (axis 0), per column
    col_softmax<<<C_DIM, 256>>>(p_rw);

    // 3) values = x @ read_w   (16384 x 4096) @ (4096 x 128)
    {
        dim3 grid(C_DIM / 128, M_TOK / 128);
        sgemm<128, 128, 16, 8, 8, false><<<grid, 256>>>(
            x, p_rw, p_vals, M_TOK, C_DIM, V_DIM, nullptr);
    }

    // 4) op bank (fused 8x GEMM + nonlinearity + mixture)
    opbank<<<M_TOK / 64, 256>>>(p_vals, logits, opW, opB, p_mix);

    // 5) out = mixed @ write_w^T * out_scale   (16384 x 128) @ (128 x 4096)
    {
        dim3 grid(V_DIM / 128, M_TOK / 128);
        sgemm<128, 128, 16, 8, 8, true><<<grid, 256>>>(
            p_mix, p_ww, out, M_TOK, V_DIM, C_DIM, oscale);
    }
}

// round 7
// speedup vs baseline: 4.9506x; 4.9506x over previous
#include <cuda_runtime.h>
#include <cuda_bf16.h>
#include <math.h>
#include <stdint.h>

#define M_TOK 16384
#define V_DIM 4096
#define C_DIM 128
#define K_NB2 128
#define N_OPS 8

// ------------------------- scratch (device globals) -------------------------
__device__ float g_rw[V_DIM * C_DIM];
__device__ float g_ww[V_DIM * C_DIM];
__device__ __nv_bfloat16 g_rwTh[C_DIM * V_DIM];   // read_w^T hi (C x V)
__device__ __nv_bfloat16 g_rwTl[C_DIM * V_DIM];
__device__ __nv_bfloat16 g_wwh[V_DIM * C_DIM];    // write_w hi (V x C) = B n x k
__device__ __nv_bfloat16 g_wwl[V_DIM * C_DIM];
__device__ __nv_bfloat16 g_valsh[M_TOK * C_DIM];
__device__ __nv_bfloat16 g_valsl[M_TOK * C_DIM];
__device__ __nv_bfloat16 g_mixh[M_TOK * C_DIM];
__device__ __nv_bfloat16 g_mixl[M_TOK * C_DIM];
__device__ __nv_bfloat16 g_wTh[N_OPS * C_DIM * C_DIM]; // [op][n][k]
__device__ __nv_bfloat16 g_wTl[N_OPS * C_DIM * C_DIM];

// ------------------------- helpers -------------------------
__device__ __forceinline__ uint32_t smem_u32(const void* p) {
    uint32_t a;
    asm("{ .reg .u64 t; cvta.to.shared.u64 t, %1; cvt.u32.u64 %0, t; }" : "=r"(a) : "l"(p));
    return a;
}
#define CP16(saddr, gptr) \
    asm volatile("cp.async.cg.shared.global [%0], [%1], 16;" :: "r"(saddr), "l"(gptr) : "memory")
#define CP_COMMIT() asm volatile("cp.async.commit_group;" ::: "memory")
template <int N> __device__ __forceinline__ void cp_wait() {
    asm volatile("cp.async.wait_group %0;" :: "n"(N) : "memory");
}
__device__ __forceinline__ void ldsm4(uint32_t& r0, uint32_t& r1, uint32_t& r2, uint32_t& r3, uint32_t a) {
    asm volatile("ldmatrix.sync.aligned.m8n8.x4.shared.b16 {%0,%1,%2,%3}, [%4];"
        : "=r"(r0), "=r"(r1), "=r"(r2), "=r"(r3) : "r"(a));
}
__device__ __forceinline__ void mma_bf16(float c[4], const uint32_t a[4], const uint32_t b[2]) {
    asm volatile(
        "mma.sync.aligned.m16n8k16.row.col.f32.bf16.bf16.f32 "
        "{%0,%1,%2,%3},{%4,%5,%6,%7},{%8,%9},{%0,%1,%2,%3};"
        : "+f"(c[0]), "+f"(c[1]), "+f"(c[2]), "+f"(c[3])
        : "r"(a[0]), "r"(a[1]), "r"(a[2]), "r"(a[3]), "r"(b[0]), "r"(b[1]));
}
__device__ __forceinline__ void split2(float a, float b, uint32_t& hi, uint32_t& lo) {
    __nv_bfloat16 ha = __float2bfloat16(a), hb = __float2bfloat16(b);
    __nv_bfloat16 la = __float2bfloat16(a - __bfloat162float(ha));
    __nv_bfloat16 lb = __float2bfloat16(b - __bfloat162float(hb));
    hi = (uint32_t)__bfloat16_as_ushort(ha) | ((uint32_t)__bfloat16_as_ushort(hb) << 16);
    lo = (uint32_t)__bfloat16_as_ushort(la) | ((uint32_t)__bfloat16_as_ushort(lb) << 16);
}
__device__ __forceinline__ void split1(float a, uint16_t& h, uint16_t& l) {
    __nv_bfloat16 ha = __float2bfloat16(a);
    __nv_bfloat16 la = __float2bfloat16(a - __bfloat162float(ha));
    h = __bfloat16_as_ushort(ha);
    l = __bfloat16_as_ushort(la);
}

// ---------------------------------------------------------------------------
// fp32 SGEMM for tiny addressing GEMMs: C = A(MxK) @ B(NxK)^T  (K=128)
// ---------------------------------------------------------------------------
__global__ __launch_bounds__(256) void sgemm_bt(
    const float* __restrict__ A, const float* __restrict__ B,
    float* __restrict__ Cm, int M, int N, int K)
{
    __shared__ float As[16][128];
    __shared__ float Bs[16][128];
    const int tid = threadIdx.x;
    const int tc = tid % 16, tr = tid / 16;
    const int m0 = blockIdx.y * 128, n0 = blockIdx.x * 128;

    float acc[8][8];
#pragma unroll
    for (int i = 0; i < 8; i++)
#pragma unroll
        for (int j = 0; j < 8; j++) acc[i][j] = 0.0f;

    for (int k0 = 0; k0 < K; k0 += 16) {
#pragma unroll
        for (int i = 0; i < 2; i++) {
            int idx = tid + i * 256;
            int row = idx / 4, c4 = idx % 4;
            float4 va = *(const float4*)&A[(size_t)(m0 + row) * K + k0 + c4 * 4];
            As[c4 * 4 + 0][row] = va.x; As[c4 * 4 + 1][row] = va.y;
            As[c4 * 4 + 2][row] = va.z; As[c4 * 4 + 3][row] = va.w;
            float4 vb = *(const float4*)&B[(size_t)(n0 + row) * K + k0 + c4 * 4];
            Bs[c4 * 4 + 0][row] = vb.x; Bs[c4 * 4 + 1][row] = vb.y;
            Bs[c4 * 4 + 2][row] = vb.z; Bs[c4 * 4 + 3][row] = vb.w;
        }
        __syncthreads();
#pragma unroll
        for (int k = 0; k < 16; k++) {
            float ra[8], rb[8];
#pragma unroll
            for (int i = 0; i < 8; i++) ra[i] = As[k][tr * 8 + i];
#pragma unroll
            for (int j = 0; j < 8; j++) rb[j] = Bs[k][tc * 8 + j];
#pragma unroll
            for (int i = 0; i < 8; i++)
#pragma unroll
                for (int j = 0; j < 8; j++) acc[i][j] += ra[i] * rb[j];
        }
        __syncthreads();
    }
#pragma unroll
    for (int i = 0; i < 8; i++) {
        const size_t base = (size_t)(m0 + tr * 8 + i) * N + n0 + tc * 8;
#pragma unroll
        for (int j = 0; j < 8; j++) Cm[base + j] = acc[i][j];
    }
}

// ---------------------------------------------------------------------------
// Column softmax over V (axis 0); write transposed bf16 hi/lo (C x V)
// ---------------------------------------------------------------------------
__global__ __launch_bounds__(256) void col_softmax_T(const float* __restrict__ S)
{
    __shared__ float col[V_DIM];
    __shared__ float red[256];
    const int c = blockIdx.x;
    const int tid = threadIdx.x;

    float m = -1e30f;
    for (int v = tid; v < V_DIM; v += 256) {
        float x = S[(size_t)v * C_DIM + c];
        col[v] = x;
        m = fmaxf(m, x);
    }
    red[tid] = m; __syncthreads();
    for (int s = 128; s > 0; s >>= 1) { if (tid < s) red[tid] = fmaxf(red[tid], red[tid + s]); __syncthreads(); }
    m = red[0]; __syncthreads();

    float sum = 0.0f;
    for (int v = tid; v < V_DIM; v += 256) { float e = expf(col[v] - m); col[v] = e; sum += e; }
    red[tid] = sum; __syncthreads();
    for (int s = 128; s > 0; s >>= 1) { if (tid < s) red[tid] += red[tid + s]; __syncthreads(); }
    const float inv = 1.0f / red[0];

    for (int v = tid; v < V_DIM; v += 256) {
        uint16_t h, l;
        split1(col[v] * inv, h, l);
        g_rwTh[(size_t)c * V_DIM + v] = __ushort_as_bfloat16(h);
        g_rwTl[(size_t)c * V_DIM + v] = __ushort_as_bfloat16(l);
    }
}

__global__ __launch_bounds__(256) void conv_ww(const float* __restrict__ W)
{
    int i = blockIdx.x * 256 + threadIdx.x;
    uint16_t h, l;
    split1(W[i], h, l);
    g_wwh[i] = __ushort_as_bfloat16(h);
    g_wwl[i] = __ushort_as_bfloat16(l);
}

__global__ __launch_bounds__(256) void prep_wT(const float* __restrict__ W)
{
    int idx = blockIdx.x * 256 + threadIdx.x;
    int op = idx >> 14;
    int rem = idx & 16383;
    int n = rem >> 7, k = rem & 127;
    uint16_t h, l;
    split1(W[op * 16384 + k * 128 + n], h, l);
    g_wTh[idx] = __ushort_as_bfloat16(h);
    g_wTl[idx] = __ushort_as_bfloat16(l);
}

// ---------------------------------------------------------------------------
// GEMM1: values = x (16384x4096 fp32) @ read_w (4096x128) -> vals bf16 hi/lo
// mma.sync bf16, hi/lo split (3 passes). 128x128 CTA tile, BK=64 double-buf.
// smem: A fp32 2x(128x72f=36864B) | Bh 2x16KB | Bl 2x16KB = 139264B
// ---------------------------------------------------------------------------
__global__ __launch_bounds__(256, 1) void mgemm1(const float* __restrict__ x)
{
    extern __shared__ char sm[];
    const uint32_t sb = smem_u32(sm);
    const int tid = threadIdx.x;
    const int lane = tid & 31, wid = tid >> 5;
    const int wr = wid & 3, wc = wid >> 2;   // 4 x 2 warps; warp tile 32x64
    const int m0 = blockIdx.x * 128;
    const float* xbase = x + (size_t)m0 * V_DIM;

    float4 apf[8];
    float acc[2][8][4];
#pragma unroll
    for (int a = 0; a < 2; a++)
#pragma unroll
        for (int b = 0; b < 8; b++)
#pragma unroll
            for (int c = 0; c < 4; c++) acc[a][b][c] = 0.0f;

    auto ldA = [&](int k0) {
#pragma unroll
        for (int i = 0; i < 8; i++) {
            int idx = tid + i * 256;
            apf[i] = *(const float4*)&xbase[(size_t)(idx >> 4) * V_DIM + k0 + (idx & 15) * 4];
        }
    };
    auto stA = [&](int s) {
        char* a = sm + s * 36864;
#pragma unroll
        for (int i = 0; i < 8; i++) {
            int idx = tid + i * 256;
            *(float4*)(a + (idx >> 4) * 288 + (idx & 15) * 16) = apf[i];
        }
    };
    auto ldB = [&](int k0, int s) {
        uint32_t bh = sb + 73728 + s * 16384;
        uint32_t bl = sb + 106496 + s * 16384;
#pragma unroll
        for (int i = 0; i < 4; i++) {
            int idx = tid + i * 256;
            int r = idx >> 3, c = idx & 7;
            uint32_t so = r * 128 + ((c ^ (r & 7)) << 4);
            CP16(bh + so, &g_rwTh[(size_t)r * V_DIM + k0 + c * 8]);
            CP16(bl + so, &g_rwTl[(size_t)r * V_DIM + k0 + c * 8]);
        }
    };

    const int ar = wr * 32 + (lane >> 2);
    const int ac = 2 * (lane & 3);
    const int br = wc * 64 + ((lane >> 4) & 1) * 8 + (lane & 7);
    const int bxr = lane & 7;
    const int bko = (lane >> 3) & 1;

    ldA(0);
    ldB(0, 0); CP_COMMIT();

    for (int ch = 0; ch < 64; ch++) {
        const int s = ch & 1;
        stA(s);
        if (ch < 63) {
            ldA((ch + 1) * 64);
            ldB((ch + 1) * 64, 1 - s); CP_COMMIT();
            cp_wait<1>();
        } else {
            cp_wait<0>();
        }
        __syncthreads();

        const char* a = sm + s * 36864;
        const uint32_t bh0 = sb + 73728 + s * 16384;
        const uint32_t bl0 = sb + 106496 + s * 16384;
#pragma unroll
        for (int ks = 0; ks < 4; ks++) {
            uint32_t Ah[2][4], Al[2][4];
#pragma unroll
            for (int mf = 0; mf < 2; mf++) {
                const char* ap = a + (ar + mf * 16) * 288;
                float2 v0 = *(const float2*)(ap + (ks * 16 + ac) * 4);
                float2 v1 = *(const float2*)(ap + 8 * 288 + (ks * 16 + ac) * 4);
                float2 v2 = *(const float2*)(ap + (ks * 16 + ac + 8) * 4);
                float2 v3 = *(const float2*)(ap + 8 * 288 + (ks * 16 + ac + 8) * 4);
                split2(v0.x, v0.y, Ah[mf][0], Al[mf][0]);
                split2(v1.x, v1.y, Ah[mf][1], Al[mf][1]);
                split2(v2.x, v2.y, Ah[mf][2], Al[mf][2]);
                split2(v3.x, v3.y, Ah[mf][3], Al[mf][3]);
            }
            uint32_t Bh[8][2], Bl[8][2];
#pragma unroll
            for (int p = 0; p < 4; p++) {
                int rr = br + p * 16;
                uint32_t so = rr * 128 + (((ks * 2 + bko) ^ bxr) << 4);
                ldsm4(Bh[2 * p][0], Bh[2 * p][1], Bh[2 * p + 1][0], Bh[2 * p + 1][1], bh0 + so);
                ldsm4(Bl[2 * p][0], Bl[2 * p][1], Bl[2 * p + 1][0], Bl[2 * p + 1][1], bl0 + so);
            }
#pragma unroll
            for (int mf = 0; mf < 2; mf++)
#pragma unroll
                for (int nf = 0; nf < 8; nf++) {
                    mma_bf16(acc[mf][nf], Ah[mf], Bh[nf]);
                    mma_bf16(acc[mf][nf], Ah[mf], Bl[nf]);
                    mma_bf16(acc[mf][nf], Al[mf], Bh[nf]);
                }
        }
        __syncthreads();
    }

    // epilogue -> vals hi/lo
#pragma unroll
    for (int mf = 0; mf < 2; mf++)
#pragma unroll
        for (int nf = 0; nf < 8; nf++) {
            int r = m0 + wr * 32 + mf * 16 + (lane >> 2);
            int c = wc * 64 + nf * 8 + 2 * (lane & 3);
            uint32_t h0, l0, h1, l1;
            split2(acc[mf][nf][0], acc[mf][nf][1], h0, l0);
            split2(acc[mf][nf][2], acc[mf][nf][3], h1, l1);
            *(uint32_t*)&g_valsh[(size_t)r * C_DIM + c] = h0;
            *(uint32_t*)&g_valsl[(size_t)r * C_DIM + c] = l0;
            *(uint32_t*)&g_valsh[(size_t)(r + 8) * C_DIM + c] = h1;
            *(uint32_t*)&g_valsl[(size_t)(r + 8) * C_DIM + c] = l1;
        }
}

// ---------------------------------------------------------------------------
// op-bank: mix = sum_i w_i * f_i(vals @ W_i + b_i), 64-row CTA tiles
// smem: Ah 16K | Al 16K | W stages 2x(32K+32K) | bias 4K = 167936B
// ---------------------------------------------------------------------------
__global__ __launch_bounds__(256, 1) void mopbank(
    const float* __restrict__ logits, const float* __restrict__ bias)
{
    extern __shared__ char sm[];
    const uint32_t sb = smem_u32(sm);
    const int tid = threadIdx.x, lane = tid & 31, wid = tid >> 5;
    const int wr = wid & 3, wc = wid >> 2;   // 4 x 2; warp tile 16x64
    const int m0 = blockIdx.x * 64;
    float* bs = (float*)(sm + 163840);

#pragma unroll
    for (int i = 0; i < 4; i++) {
        int idx = tid + i * 256;
        int r = idx >> 4, c = idx & 15;
        uint32_t so = r * 256 + ((c ^ (r & 7)) << 4);
        CP16(sb + so, &g_valsh[(size_t)(m0 + r) * C_DIM + c * 8]);
        CP16(sb + 16384 + so, &g_valsl[(size_t)(m0 + r) * C_DIM + c * 8]);
    }
    auto ldW = [&](int op, int s) {
        uint32_t wh = sb + 32768 + s * 65536;
        uint32_t wl = sb + 65536 + s * 65536;
#pragma unroll
        for (int i = 0; i < 8; i++) {
            int idx = tid + i * 256;
            int r = idx >> 4, c = idx & 15;
            uint32_t so = r * 256 + ((c ^ (r & 7)) << 4);
            CP16(wh + so, &g_wTh[(size_t)op * 16384 + r * C_DIM + c * 8]);
            CP16(wl + so, &g_wTl[(size_t)op * 16384 + r * C_DIM + c * 8]);
        }
    };
    ldW(0, 0); CP_COMMIT();

#pragma unroll
    for (int i = 0; i < 4; i++) bs[tid + i * 256] = bias[tid + i * 256];

    float wv[N_OPS];
    float mx = -1e30f;
#pragma unroll
    for (int i = 0; i < N_OPS; i++) { wv[i] = __ldg(&logits[i]); mx = fmaxf(mx, wv[i]); }
    float sumw = 0.0f;
#pragma unroll
    for (int i = 0; i < N_OPS; i++) { wv[i] = expf(wv[i] - mx); sumw += wv[i]; }
#pragma unroll
    for (int i = 0; i < N_OPS; i++) wv[i] /= sumw;

    float res[8][4];
#pragma unroll
    for (int n = 0; n < 8; n++)
#pragma unroll
        for (int j = 0; j < 4; j++) res[n][j] = 0.0f;

    const int arow = wr * 16 + (lane & 15);
    const int ako = lane >> 4;
    const int brow = wc * 64 + ((lane >> 4) & 1) * 8 + (lane & 7);
    const int bko = (lane >> 3) & 1;

#pragma unroll 1
    for (int op = 0; op < N_OPS; op++) {
        const int s = op & 1;
        if (op < 7) { ldW(op + 1, 1 - s); CP_COMMIT(); cp_wait<1>(); }
        else cp_wait<0>();
        __syncthreads();

        float acc[8][4];
#pragma unroll
        for (int n = 0; n < 8; n++)
#pragma unroll
            for (int j = 0; j < 4; j++) acc[n][j] = 0.0f;

        const uint32_t wh0 = sb + 32768 + s * 65536;
        const uint32_t wl0 = sb + 65536 + s * 65536;
#pragma unroll
        for (int ks = 0; ks < 8; ks++) {
            uint32_t Ah[4], Al[4], Bh[8][2], Bl[8][2];
            uint32_t ac16 = (uint32_t)((ks * 2 + ako) ^ (arow & 7));
            ldsm4(Ah[0], Ah[1], Ah[2], Ah[3], sb + arow * 256 + (ac16 << 4));
            ldsm4(Al[0], Al[1], Al[2], Al[3], sb + 16384 + arow * 256 + (ac16 << 4));
#pragma unroll
            for (int p = 0; p < 4; p++) {
                int rr = brow + p * 16;
                uint32_t so = rr * 256 + (((ks * 2 + bko) ^ (rr & 7)) << 4);
                ldsm4(Bh[2 * p][0], Bh[2 * p][1], Bh[2 * p + 1][0], Bh[2 * p + 1][1], wh0 + so);
                ldsm4(Bl[2 * p][0], Bl[2 * p][1], Bl[2 * p + 1][0], Bl[2 * p + 1][1], wl0 + so);
            }
#pragma unroll
            for (int nf = 0; nf < 8; nf++) {
                mma_bf16(acc[nf], Ah, Bh[nf]);
                mma_bf16(acc[nf], Ah, Bl[nf]);
                mma_bf16(acc[nf], Al, Bh[nf]);
            }
        }
        const float w = wv[op];
#pragma unroll
        for (int nf = 0; nf < 8; nf++)
#pragma unroll
            for (int j = 0; j < 4; j++) {
                int col = wc * 64 + nf * 8 + 2 * (lane & 3) + (j & 1);
                float v = acc[nf][j] + bs[op * C_DIM + col];
                float f;
                switch (op) {
                    case 0: f = v; break;
                    case 1: f = fmaxf(v, 0.0f); break;
                    case 2: f = 0.5f * v * (1.0f + erff(v * 0.70710678118654752f)); break;
                    case 3: f = v * v; break;
                    case 4: f = -v; break;
                    case 5: f = fabsf(v); break;
                    case 6: f = tanhf(v); break;
                    default: f = 1.0f / (1.0f + expf(-v)); break;
                }
                res[nf][j] += w * f;
            }
        __syncthreads();
    }

#pragma unroll
    for (int nf = 0; nf < 8; nf++) {
        int r = m0 + wr * 16 + (lane >> 2);
        int c = wc * 64 + nf * 8 + 2 * (lane & 3);
        uint32_t h0, l0, h1, l1;
        split2(res[nf][0], res[nf][1], h0, l0);
        split2(res[nf][2], res[nf][3], h1, l1);
        *(uint32_t*)&g_mixh[(size_t)r * C_DIM + c] = h0;
        *(uint32_t*)&g_mixl[(size_t)r * C_DIM + c] = l0;
        *(uint32_t*)&g_mixh[(size_t)(r + 8) * C_DIM + c] = h1;
        *(uint32_t*)&g_mixl[(size_t)(r + 8) * C_DIM + c] = l1;
    }
}

// ---------------------------------------------------------------------------
// GEMM2: out = mix (16384x128) @ write_w^T (128x4096) * out_scale
// Persistent m-tile CTAs (128x128 A resident), loop 32 n-tiles, B double-buf.
// smem: Ah 32K | Al 32K | B stages 2x(32K+32K) = 196608B
// ---------------------------------------------------------------------------
__global__ __launch_bounds__(256, 1) void mgemm2(
    float* __restrict__ out, const float* __restrict__ oscale)
{
    extern __shared__ char sm[];
    const uint32_t sb = smem_u32(sm);
    const int tid = threadIdx.x, lane = tid & 31, wid = tid >> 5;
    const int wr = wid & 3, wc = wid >> 2;   // 4 x 2; warp tile 32x64
    const int m0 = blockIdx.x * 128;

#pragma unroll
    for (int i = 0; i < 8; i++) {
        int idx = tid + i * 256;
        int r = idx >> 4, c = idx & 15;
        uint32_t so = r * 256 + ((c ^ (r & 7)) << 4);
        CP16(sb + so, &g_mixh[(size_t)(m0 + r) * C_DIM + c * 8]);
        CP16(sb + 32768 + so, &g_mixl[(size_t)(m0 + r) * C_DIM + c * 8]);
    }
    auto ldB = [&](int n0, int s) {
        uint32_t bh = sb + 65536 + s * 65536;
        uint32_t bl = sb + 98304 + s * 65536;
#pragma unroll
        for (int i = 0; i < 8; i++) {
            int idx = tid + i * 256;
            int r = idx >> 4, c = idx & 15;
            uint32_t so = r * 256 + ((c ^ (r & 7)) << 4);
            CP16(bh + so, &g_wwh[(size_t)(n0 + r) * C_DIM + c * 8]);
            CP16(bl + so, &g_wwl[(size_t)(n0 + r) * C_DIM + c * 8]);
        }
    };
    ldB(0, 0); CP_COMMIT();
    const float alpha = __ldg(oscale);

    const int arow = wr * 32 + (lane & 15);
    const int ako = lane >> 4;
    const int brow = wc * 64 + ((lane >> 4) & 1) * 8 + (lane & 7);
    const int bko = (lane >> 3) & 1;

#pragma unroll 1
    for (int nt = 0; nt < 32; nt++) {
        const int s = nt & 1;
        if (nt < 31) { ldB((nt + 1) * 128, 1 - s); CP_COMMIT(); cp_wait<1>(); }
        else cp_wait<0>();
        __syncthreads();

        float acc[2][8][4];
#pragma unroll
        for (int a = 0; a < 2; a++)
#pragma unroll
            for (int b = 0; b < 8; b++)
#pragma unroll
                for (int c = 0; c < 4; c++) acc[a][b][c] = 0.0f;

        const uint32_t bh0 = sb + 65536 + s * 65536;
        const uint32_t bl0 = sb + 98304 + s * 65536;
#pragma unroll
        for (int ks = 0; ks < 8; ks++) {
            uint32_t Ah[2][4], Al[2][4], Bh[8][2], Bl[8][2];
#pragma unroll
            for (int mf = 0; mf < 2; mf++) {
                uint32_t rr = arow + mf * 16;
                uint32_t c16 = (uint32_t)((ks * 2 + ako) ^ (rr & 7));
                ldsm4(Ah[mf][0], Ah[mf][1], Ah[mf][2], Ah[mf][3], sb + rr * 256 + (c16 << 4));
                ldsm4(Al[mf][0], Al[mf][1], Al[mf][2], Al[mf][3], sb + 32768 + rr * 256 + (c16 << 4));
            }
#pragma unroll
            for (int p = 0; p < 4; p++) {
                int rr = brow + p * 16;
                uint32_t so = rr * 256 + (((ks * 2 + bko) ^ (rr & 7)) << 4);
                ldsm4(Bh[2 * p][0], Bh[2 * p][1], Bh[2 * p + 1][0], Bh[2 * p + 1][1], bh0 + so);
                ldsm4(Bl[2 * p][0], Bl[2 * p][1], Bl[2 * p + 1][0], Bl[2 * p + 1][1], bl0 + so);
            }
#pragma unroll
            for (int mf = 0; mf < 2; mf++)
#pragma unroll
                for (int nf = 0; nf < 8; nf++) {
                    mma_bf16(acc[mf][nf], Ah[mf], Bh[nf]);
                    mma_bf16(acc[mf][nf], Ah[mf], Bl[nf]);
                    mma_bf16(acc[mf][nf], Al[mf], Bh[nf]);
                }
        }
#pragma unroll
        for (int mf = 0; mf < 2; mf++)
#pragma unroll
            for (int nf = 0; nf < 8; nf++) {
                int r = m0 + wr * 32 + mf * 16 + (lane >> 2);
                int c = nt * 128 + wc * 64 + nf * 8 + 2 * (lane & 3);
                float2 v0 = make_float2(acc[mf][nf][0] * alpha, acc[mf][nf][1] * alpha);
                float2 v1 = make_float2(acc[mf][nf][2] * alpha, acc[mf][nf][3] * alpha);
                *(float2*)&out[(size_t)r * V_DIM + c] = v0;
                *(float2*)&out[(size_t)(r + 8) * V_DIM + c] = v1;
            }
        __syncthreads();
    }
}

// ---------------------------------------------------------------------------
extern "C" void kernel_launch(void* const* d_in, const int* in_sizes, int n_in,
                              void* d_out, int out_size)
{
    const float* x      = (const float*)d_in[0];
    const float* basis  = (const float*)d_in[1];
    const float* rcoef  = (const float*)d_in[2];
    const float* wcoef  = (const float*)d_in[3];
    const float* logits = (const float*)d_in[4];
    const float* opW    = (const float*)d_in[5];
    const float* opB    = (const float*)d_in[6];
    const float* oscale = (const float*)d_in[7];
    float* out = (float*)d_out;

    float *p_rw, *p_ww;
    cudaGetSymbolAddress((void**)&p_rw, g_rw);
    cudaGetSymbolAddress((void**)&p_ww, g_ww);

    static bool attr_done = false;
    if (!attr_done) {
        cudaFuncSetAttribute(mgemm1,  cudaFuncAttributeMaxDynamicSharedMemorySize, 139264);
        cudaFuncSetAttribute(mopbank, cudaFuncAttributeMaxDynamicSharedMemorySize, 167936);
        cudaFuncSetAttribute(mgemm2,  cudaFuncAttributeMaxDynamicSharedMemorySize, 196608);
        attr_done = true;
    }

    // 1) addressing scores (fp32, tiny)
    {
        dim3 grid(1, V_DIM / 128);
        sgemm_bt<<<grid, 256>>>(basis, rcoef, p_rw, V_DIM, C_DIM, K_NB2);
        sgemm_bt<<<grid, 256>>>(basis, wcoef, p_ww, V_DIM, C_DIM, K_NB2);
    }
    // 2) prep: softmax+T+split, ww split, op-W T+split
    col_softmax_T<<<C_DIM, 256>>>(p_rw);
    conv_ww<<<V_DIM * C_DIM / 256, 256>>>(p_ww);
    prep_wT<<<N_OPS * C_DIM * C_DIM / 256, 256>>>(opW);

    // 3) values = x @ read_w  (mma.sync bf16 split)
    mgemm1<<<M_TOK / 128, 256, 139264>>>(x);

    // 4) op bank
    mopbank<<<M_TOK / 64, 256, 167936>>>(logits, opB);

    // 5) out = mix @ write_w^T * out_scale
    mgemm2<<<M_TOK / 128, 256, 196608>>>(out, oscale);
}